// round 4
// baseline (speedup 1.0000x reference)
#include <cuda_runtime.h>
#include <math.h>

// Problem constants
#define BB 2
#define SS 2048
#define DD 1024
#define HH 16
#define DHH 64
#define ROWS (BB*SS)        // 4096
#define EPSF 1e-5f

// ---------------- scratch (device globals, no allocation) ----------------
__device__ float g_ln  [(size_t)ROWS*DD];
__device__ float g_q   [(size_t)ROWS*DD];
__device__ float g_k   [(size_t)ROWS*DD];
__device__ float g_v   [(size_t)ROWS*DD];
__device__ float g_attn[(size_t)ROWS*DD];
__device__ float g_x1  [(size_t)ROWS*DD];
__device__ float g_ln2 [(size_t)ROWS*DD];
__device__ float g_h   [(size_t)ROWS*4*DD];
__device__ float g_glu [(size_t)ROWS*2*DD];

// ---------------- LayerNorm: one block per row, 256 threads ----------------
__global__ void ln_kernel(const float* __restrict__ x,
                          const float* __restrict__ gamma,
                          const float* __restrict__ beta,
                          float* __restrict__ y) {
    const int row = blockIdx.x;
    const int tid = threadIdx.x;           // 256 threads, 4 floats each
    const float* xr = x + (size_t)row * DD;
    float4 v = *(const float4*)(xr + tid * 4);
    float s  = v.x + v.y + v.z + v.w;
    float ss = v.x*v.x + v.y*v.y + v.z*v.z + v.w*v.w;
    #pragma unroll
    for (int off = 16; off; off >>= 1) {
        s  += __shfl_xor_sync(0xffffffffu, s,  off);
        ss += __shfl_xor_sync(0xffffffffu, ss, off);
    }
    __shared__ float sh[8], sh2[8];
    if ((tid & 31) == 0) { sh[tid >> 5] = s; sh2[tid >> 5] = ss; }
    __syncthreads();
    float tot = 0.f, tot2 = 0.f;
    #pragma unroll
    for (int i = 0; i < 8; i++) { tot += sh[i]; tot2 += sh2[i]; }
    const float mean = tot * (1.f / DD);
    const float var  = tot2 * (1.f / DD) - mean * mean;
    const float inv  = rsqrtf(var + EPSF);
    float4 g = *(const float4*)(gamma + tid * 4);
    float4 b = *(const float4*)(beta  + tid * 4);
    float4 o;
    o.x = g.x * (v.x - mean) * inv + b.x;
    o.y = g.y * (v.y - mean) * inv + b.y;
    o.z = g.z * (v.z - mean) * inv + b.z;
    o.w = g.w * (v.w - mean) * inv + b.w;
    *(float4*)(y + (size_t)row * DD + tid * 4) = o;
}

// ---------------- SGEMM 128x128x8, 256 threads, 8x8 per thread ----------------
// A [M,K] row-major, B [K,N] row-major, C [M,N].
// EPI 0: C = A@B
// EPI 1: C = A@B scattered to [B,H,S,DH] head layout
// EPI 2: C = A@B + X  (X [M,N])
template<int EPI>
__global__ __launch_bounds__(256, 2)
void sgemm_kernel(const float* __restrict__ A, const float* __restrict__ B,
                  float* __restrict__ C, const float* __restrict__ X,
                  int M, int N, int K) {
    __shared__ __align__(16) float As[8][132];   // transposed A tile, padded
    __shared__ __align__(16) float Bs[8][128];
    const int tid = threadIdx.x;
    const int tx = tid & 15, ty = tid >> 4;
    const int m0 = blockIdx.y << 7, n0 = blockIdx.x << 7;

    const int a_m = tid >> 1, a_k = (tid & 1) << 2;
    const int b_k = tid >> 5, b_n = (tid & 31) << 2;

    const float* Ag = A + (size_t)(m0 + a_m) * K + a_k;
    const float* Bg = B + (size_t)b_k * N + (n0 + b_n);

    float acc[8][8];
    #pragma unroll
    for (int i = 0; i < 8; i++)
        #pragma unroll
        for (int j = 0; j < 8; j++) acc[i][j] = 0.f;

    for (int kk = 0; kk < K; kk += 8) {
        float4 av = *(const float4*)(Ag + kk);
        float4 bv = *(const float4*)(Bg + (size_t)kk * N);
        __syncthreads();
        As[a_k + 0][a_m] = av.x;
        As[a_k + 1][a_m] = av.y;
        As[a_k + 2][a_m] = av.z;
        As[a_k + 3][a_m] = av.w;
        *(float4*)(&Bs[b_k][b_n]) = bv;
        __syncthreads();
        #pragma unroll
        for (int k = 0; k < 8; k++) {
            float ar[8], br[8];
            *(float4*)(ar)     = *(const float4*)(&As[k][ty << 3]);
            *(float4*)(ar + 4) = *(const float4*)(&As[k][(ty << 3) + 4]);
            *(float4*)(br)     = *(const float4*)(&Bs[k][tx << 3]);
            *(float4*)(br + 4) = *(const float4*)(&Bs[k][(tx << 3) + 4]);
            #pragma unroll
            for (int i = 0; i < 8; i++)
                #pragma unroll
                for (int j = 0; j < 8; j++)
                    acc[i][j] += ar[i] * br[j];
        }
    }

    #pragma unroll
    for (int i = 0; i < 8; i++) {
        const int m = m0 + (ty << 3) + i;
        float4 c0 = make_float4(acc[i][0], acc[i][1], acc[i][2], acc[i][3]);
        float4 c1 = make_float4(acc[i][4], acc[i][5], acc[i][6], acc[i][7]);
        if (EPI == 1) {
            // scatter row m (= b*S+s), cols n..n+7 (= h*64+dh) into [B,H,S,DH]
            const int bb = m >> 11, srow = m & 2047;
            const int n = n0 + (tx << 3);
            const int h0 = n >> 6, dh0 = n & 63;            // 8 | 64 => one head
            const size_t base = (((size_t)(bb * HH + h0)) * SS + srow) * DHH + dh0;
            *(float4*)(C + base)     = c0;
            *(float4*)(C + base + 4) = c1;
        } else {
            const size_t off = (size_t)m * N + n0 + (tx << 3);
            if (EPI == 2) {
                float4 x0 = *(const float4*)(X + off);
                float4 x1 = *(const float4*)(X + off + 4);
                c0.x += x0.x; c0.y += x0.y; c0.z += x0.z; c0.w += x0.w;
                c1.x += x1.x; c1.y += x1.y; c1.z += x1.z; c1.w += x1.w;
            }
            *(float4*)(C + off)     = c0;
            *(float4*)(C + off + 4) = c1;
        }
    }
}

// ---------------- Flash attention (fp32), 64x64 tiles, causal ----------------
#define AT_PAD 68
#define ATT_SMEM (4 * 64 * AT_PAD * 4)

__global__ void attn_kernel(const float* __restrict__ Q, const float* __restrict__ K,
                            const float* __restrict__ V, const int* __restrict__ amask,
                            float* __restrict__ O) {
    extern __shared__ __align__(16) float sm[];
    float* Qs = sm;                   // [dh][m]  64x68
    float* Ks = Qs + 64 * AT_PAD;     // [dh][n]
    float* Vs = Ks + 64 * AT_PAD;     // [n][dh]
    float* Ps = Vs + 64 * AT_PAD;     // [n][m]
    __shared__ int mk[64];

    const int qb = blockIdx.x;        // query block 0..31
    const int bh = blockIdx.y;        // 0..31 (b*16+h)
    const int b  = bh >> 4;
    const int tid = threadIdx.x;      // 256
    const int tx = tid & 15, ty = tid >> 4;

    const float* Qg = Q + (size_t)bh * SS * DHH + (size_t)qb * 64 * DHH;
    const float* Kg = K + (size_t)bh * SS * DHH;
    const float* Vg = V + (size_t)bh * SS * DHH;

    // load Q tile transposed: Qs[dh][m]
    for (int idx = tid; idx < 64 * 16; idx += 256) {
        const int m  = idx >> 4;
        const int d4 = (idx & 15) << 2;
        float4 v = *(const float4*)(Qg + m * DHH + d4);
        Qs[(d4 + 0) * AT_PAD + m] = v.x;
        Qs[(d4 + 1) * AT_PAD + m] = v.y;
        Qs[(d4 + 2) * AT_PAD + m] = v.z;
        Qs[(d4 + 3) * AT_PAD + m] = v.w;
    }

    float o[4][4];
    float mrow[4], lrow[4];
    #pragma unroll
    for (int i = 0; i < 4; i++) {
        mrow[i] = -1e30f; lrow[i] = 0.f;
        #pragma unroll
        for (int j = 0; j < 4; j++) o[i][j] = 0.f;
    }
    const int qrow0 = qb * 64 + ty * 4;   // this thread's first query (within S)

    for (int kb = 0; kb <= qb; kb++) {
        __syncthreads();   // previous iter's PV reads of Ks/Vs/Ps are done
        for (int idx = tid; idx < 64 * 16; idx += 256) {
            const int n  = idx >> 4;
            const int d4 = (idx & 15) << 2;
            float4 kv = *(const float4*)(Kg + (size_t)(kb * 64 + n) * DHH + d4);
            Ks[(d4 + 0) * AT_PAD + n] = kv.x;
            Ks[(d4 + 1) * AT_PAD + n] = kv.y;
            Ks[(d4 + 2) * AT_PAD + n] = kv.z;
            Ks[(d4 + 3) * AT_PAD + n] = kv.w;
            float4 vv = *(const float4*)(Vg + (size_t)(kb * 64 + n) * DHH + d4);
            *(float4*)(Vs + n * AT_PAD + d4) = vv;
        }
        if (tid < 64) mk[tid] = amask[b * SS + kb * 64 + tid];
        __syncthreads();

        // S = Q @ K^T  (4x4 fragment per thread)
        float s[4][4];
        #pragma unroll
        for (int i = 0; i < 4; i++)
            #pragma unroll
            for (int j = 0; j < 4; j++) s[i][j] = 0.f;
        #pragma unroll 4
        for (int k = 0; k < 64; k++) {
            float4 a4 = *(const float4*)(Qs + k * AT_PAD + (ty << 2));
            float4 b4 = *(const float4*)(Ks + k * AT_PAD + (tx << 2));
            const float ar[4] = {a4.x, a4.y, a4.z, a4.w};
            const float br[4] = {b4.x, b4.y, b4.z, b4.w};
            #pragma unroll
            for (int i = 0; i < 4; i++)
                #pragma unroll
                for (int j = 0; j < 4; j++)
                    s[i][j] += ar[i] * br[j];
        }

        // scale + causal + key mask
        #pragma unroll
        for (int i = 0; i < 4; i++) {
            const int qg = qrow0 + i;
            #pragma unroll
            for (int j = 0; j < 4; j++) {
                const int kg = kb * 64 + tx * 4 + j;
                float val = s[i][j] * 0.125f;       // 1/sqrt(64)
                if (kg > qg || mk[tx * 4 + j] == 0) val = -1e30f;
                s[i][j] = val;
            }
        }

        // online softmax (rows split across 16 lanes)
        #pragma unroll
        for (int i = 0; i < 4; i++) {
            float rm = fmaxf(fmaxf(s[i][0], s[i][1]), fmaxf(s[i][2], s[i][3]));
            #pragma unroll
            for (int off = 8; off; off >>= 1)
                rm = fmaxf(rm, __shfl_xor_sync(0xffffffffu, rm, off));
            const float mnew  = fmaxf(mrow[i], rm);
            const float alpha = __expf(mrow[i] - mnew);
            float rs = 0.f;
            #pragma unroll
            for (int j = 0; j < 4; j++) {
                const float p = __expf(s[i][j] - mnew);
                s[i][j] = p;
                rs += p;
            }
            #pragma unroll
            for (int off = 8; off; off >>= 1)
                rs += __shfl_xor_sync(0xffffffffu, rs, off);
            lrow[i] = lrow[i] * alpha + rs;
            mrow[i] = mnew;
            #pragma unroll
            for (int j = 0; j < 4; j++) o[i][j] *= alpha;
        }

        // stage P transposed: Ps[n][m]
        #pragma unroll
        for (int j = 0; j < 4; j++) {
            float4 pv = make_float4(s[0][j], s[1][j], s[2][j], s[3][j]);
            *(float4*)(Ps + (tx * 4 + j) * AT_PAD + (ty << 2)) = pv;
        }
        __syncthreads();

        // O += P @ V
        #pragma unroll 4
        for (int k = 0; k < 64; k++) {
            float4 p4 = *(const float4*)(Ps + k * AT_PAD + (ty << 2));
            float4 v4 = *(const float4*)(Vs + k * AT_PAD + (tx << 2));
            const float pr[4] = {p4.x, p4.y, p4.z, p4.w};
            const float vr[4] = {v4.x, v4.y, v4.z, v4.w};
            #pragma unroll
            for (int i = 0; i < 4; i++)
                #pragma unroll
                for (int j = 0; j < 4; j++)
                    o[i][j] += pr[i] * vr[j];
        }
    }

    // finalize + write back to [B,S,D] layout for the Wo GEMM
    const int h = bh & 15;
    #pragma unroll
    for (int i = 0; i < 4; i++) {
        const int qrow = qrow0 + i;
        const float inv = 1.f / lrow[i];
        float4 r = make_float4(o[i][0] * inv, o[i][1] * inv, o[i][2] * inv, o[i][3] * inv);
        *(float4*)(O + ((size_t)(b * SS + qrow)) * DD + h * DHH + tx * 4) = r;
    }
}

// ---------------- GLU: g = left * sigmoid(right) ----------------
__global__ void glu_kernel(const float* __restrict__ h, float* __restrict__ g) {
    const int idx = blockIdx.x * blockDim.x + threadIdx.x;  // one float4 each
    const int r  = idx >> 9;        // 512 float4 per output row (2048 floats)
    const int c4 = (idx & 511) << 2;
    float4 l = *(const float4*)(h + (size_t)r * (4 * DD) + c4);
    float4 q = *(const float4*)(h + (size_t)r * (4 * DD) + 2 * DD + c4);
    float4 o;
    o.x = l.x / (1.f + __expf(-q.x));
    o.y = l.y / (1.f + __expf(-q.y));
    o.z = l.z / (1.f + __expf(-q.z));
    o.w = l.w / (1.f + __expf(-q.w));
    *(float4*)(g + (size_t)r * (2 * DD) + c4) = o;
}

// ---------------- host launcher ----------------
extern "C" void kernel_launch(void* const* d_in, const int* in_sizes, int n_in,
                              void* d_out, int out_size) {
    const float* x      = (const float*)d_in[0];
    const int*   amask  = (const int*)  d_in[1];
    const float* Wq     = (const float*)d_in[2];
    const float* Wk     = (const float*)d_in[3];
    const float* Wv     = (const float*)d_in[4];
    const float* Wo     = (const float*)d_in[5];
    const float* W1     = (const float*)d_in[6];
    const float* W2     = (const float*)d_in[7];
    const float* gamma1 = (const float*)d_in[8];
    const float* beta1  = (const float*)d_in[9];
    const float* gamma2 = (const float*)d_in[10];
    const float* beta2  = (const float*)d_in[11];
    float* out = (float*)d_out;

    float *p_ln, *p_q, *p_k, *p_v, *p_attn, *p_x1, *p_ln2, *p_h, *p_glu;
    cudaGetSymbolAddress((void**)&p_ln,   g_ln);
    cudaGetSymbolAddress((void**)&p_q,    g_q);
    cudaGetSymbolAddress((void**)&p_k,    g_k);
    cudaGetSymbolAddress((void**)&p_v,    g_v);
    cudaGetSymbolAddress((void**)&p_attn, g_attn);
    cudaGetSymbolAddress((void**)&p_x1,   g_x1);
    cudaGetSymbolAddress((void**)&p_ln2,  g_ln2);
    cudaGetSymbolAddress((void**)&p_h,    g_h);
    cudaGetSymbolAddress((void**)&p_glu,  g_glu);

    cudaFuncSetAttribute(attn_kernel,
                         cudaFuncAttributeMaxDynamicSharedMemorySize, ATT_SMEM);

    const dim3 gN1024(DD / 128, ROWS / 128);       // (8, 32)
    const dim3 gN4096(4 * DD / 128, ROWS / 128);   // (32, 32)

    // 1. ln1
    ln_kernel<<<ROWS, 256>>>(x, gamma1, beta1, p_ln);
    // 2. QKV projections (head-scatter epilogue)
    sgemm_kernel<1><<<gN1024, 256>>>(p_ln, Wq, p_q, nullptr, ROWS, DD, DD);
    sgemm_kernel<1><<<gN1024, 256>>>(p_ln, Wk, p_k, nullptr, ROWS, DD, DD);
    sgemm_kernel<1><<<gN1024, 256>>>(p_ln, Wv, p_v, nullptr, ROWS, DD, DD);
    // 3. causal flash attention
    attn_kernel<<<dim3(SS / 64, BB * HH), 256, ATT_SMEM>>>(p_q, p_k, p_v, amask, p_attn);
    // 4. Wo + residual -> x1
    sgemm_kernel<2><<<gN1024, 256>>>(p_attn, Wo, p_x1, x, ROWS, DD, DD);
    // 5. ln2
    ln_kernel<<<ROWS, 256>>>(p_x1, gamma2, beta2, p_ln2);
    // 6. W1 (D -> 4D)
    sgemm_kernel<0><<<gN4096, 256>>>(p_ln2, W1, p_h, nullptr, ROWS, 4 * DD, DD);
    // 7. GLU
    glu_kernel<<<(ROWS * 2 * DD / 4) / 256, 256>>>(p_h, p_glu);
    // 8. W2 + residual -> out
    sgemm_kernel<2><<<gN1024, 256>>>(p_glu, W2, out, p_x1, ROWS, DD, 2 * DD);
}

// round 7
// speedup vs baseline: 1.5168x; 1.5168x over previous
#include <cuda_runtime.h>
#include <cuda_bf16.h>
#include <cstdint>
#include <math.h>

// Problem constants
#define BB 2
#define SS 2048
#define DD 1024
#define HH 16
#define DHH 64
#define ROWS (BB*SS)        // 4096
#define EPSF 1e-5f

// ======================= scratch (device globals) =======================
__device__ float g_q   [(size_t)ROWS*DD];
__device__ float g_k   [(size_t)ROWS*DD];
__device__ float g_v   [(size_t)ROWS*DD];
__device__ float g_x1  [(size_t)ROWS*DD];
__device__ float g_h   [(size_t)ROWS*4*DD];

// split-bf16 activations (hi/lo)
__device__ __nv_bfloat16 g_a1h[(size_t)ROWS*DD],   g_a1l[(size_t)ROWS*DD];
__device__ __nv_bfloat16 g_ath[(size_t)ROWS*DD],   g_atl[(size_t)ROWS*DD];
__device__ __nv_bfloat16 g_l2h[(size_t)ROWS*DD],   g_l2l[(size_t)ROWS*DD];
__device__ __nv_bfloat16 g_gh [(size_t)ROWS*2*DD], g_gl [(size_t)ROWS*2*DD];

// transposed split-bf16 weights: [N, K] K-major
__device__ __nv_bfloat16 g_wqh[(size_t)DD*DD], g_wql[(size_t)DD*DD];
__device__ __nv_bfloat16 g_wkh[(size_t)DD*DD], g_wkl[(size_t)DD*DD];
__device__ __nv_bfloat16 g_wvh[(size_t)DD*DD], g_wvl[(size_t)DD*DD];
__device__ __nv_bfloat16 g_woh[(size_t)DD*DD], g_wol[(size_t)DD*DD];
__device__ __nv_bfloat16 g_w1h[(size_t)DD*4*DD], g_w1l[(size_t)DD*4*DD];
__device__ __nv_bfloat16 g_w2h[(size_t)2*DD*DD], g_w2l[(size_t)2*DD*DD];

__device__ __forceinline__ void bf16split(float v, __nv_bfloat16& h, __nv_bfloat16& l){
    h = __float2bfloat16(v);
    l = __float2bfloat16(v - __bfloat162float(h));
}

// m16n8k16 bf16 MMA, fp32 accumulate (baseline PTX, works on non-'a' targets)
__device__ __forceinline__ void mma16816(float* c, const uint32_t* a, const uint32_t* b){
    asm volatile(
        "mma.sync.aligned.m16n8k16.row.col.f32.bf16.bf16.f32 "
        "{%0,%1,%2,%3}, {%4,%5,%6,%7}, {%8,%9}, {%0,%1,%2,%3};"
        : "+f"(c[0]), "+f"(c[1]), "+f"(c[2]), "+f"(c[3])
        : "r"(a[0]), "r"(a[1]), "r"(a[2]), "r"(a[3]), "r"(b[0]), "r"(b[1]));
}

// ======================= split-bf16 MMA GEMM =======================
// C[M,Nn] = (Ah+Al)[M,K] @ (Bh+Bl)[Nn,K]^T   (B pre-transposed, K-major)
// EPI 0: plain fp32   EPI 1: head-scatter fp32   EPI 2: +X residual fp32
// CTA tile 128x128, K-chunk 32, 8 warps (2x4), warp tile 64x32.
#define KC 32
#define APAD 40

template<int EPI>
__global__ __launch_bounds__(256)
void mma_gemm(const __nv_bfloat16* __restrict__ Ah, const __nv_bfloat16* __restrict__ Al,
              const __nv_bfloat16* __restrict__ Bh, const __nv_bfloat16* __restrict__ Bl,
              float* __restrict__ C, const float* __restrict__ X, int Nn, int K) {
    __shared__ __align__(16) __nv_bfloat16 Ash[128][APAD], Asl[128][APAD];
    __shared__ __align__(16) __nv_bfloat16 Bsh[128][APAD], Bsl[128][APAD];

    const int tid  = threadIdx.x;
    const int wid  = tid >> 5, lane = tid & 31;
    const int wm   = wid & 1, wn = wid >> 1;       // warp grid 2(m) x 4(n)
    const int m0   = blockIdx.y << 7, n0 = blockIdx.x << 7;

    // staging assignment: idx = tid*2 + {0,1}; row = idx>>2, c8 = (idx&3)*8
    const int r_a  = tid >> 1;
    const int c8a  = (tid & 1) << 4;               // 0 or 16 (two uint4 = 16 elems)

    float acc[4][4][4];
    #pragma unroll
    for (int mt = 0; mt < 4; mt++)
        #pragma unroll
        for (int nt = 0; nt < 4; nt++)
            #pragma unroll
            for (int j = 0; j < 4; j++) acc[mt][nt][j] = 0.f;

    const int nc = K / KC;
    uint4 sAh[2], sAl[2], sBh[2], sBl[2];

    // prefetch chunk 0
    {
        const __nv_bfloat16* pAh = Ah + (size_t)(m0 + r_a) * K + c8a;
        const __nv_bfloat16* pAl = Al + (size_t)(m0 + r_a) * K + c8a;
        const __nv_bfloat16* pBh = Bh + (size_t)(n0 + r_a) * K + c8a;
        const __nv_bfloat16* pBl = Bl + (size_t)(n0 + r_a) * K + c8a;
        sAh[0] = *(const uint4*)(pAh);     sAh[1] = *(const uint4*)(pAh + 8);
        sAl[0] = *(const uint4*)(pAl);     sAl[1] = *(const uint4*)(pAl + 8);
        sBh[0] = *(const uint4*)(pBh);     sBh[1] = *(const uint4*)(pBh + 8);
        sBl[0] = *(const uint4*)(pBl);     sBl[1] = *(const uint4*)(pBl + 8);
    }

    for (int kc = 0; kc < nc; kc++){
        __syncthreads();   // previous compute done before overwriting smem
        *(uint4*)&Ash[r_a][c8a]     = sAh[0];  *(uint4*)&Ash[r_a][c8a + 8] = sAh[1];
        *(uint4*)&Asl[r_a][c8a]     = sAl[0];  *(uint4*)&Asl[r_a][c8a + 8] = sAl[1];
        *(uint4*)&Bsh[r_a][c8a]     = sBh[0];  *(uint4*)&Bsh[r_a][c8a + 8] = sBh[1];
        *(uint4*)&Bsl[r_a][c8a]     = sBl[0];  *(uint4*)&Bsl[r_a][c8a + 8] = sBl[1];
        __syncthreads();

        // prefetch next chunk while computing this one
        if (kc + 1 < nc){
            const int k0 = (kc + 1) * KC;
            const __nv_bfloat16* pAh = Ah + (size_t)(m0 + r_a) * K + k0 + c8a;
            const __nv_bfloat16* pAl = Al + (size_t)(m0 + r_a) * K + k0 + c8a;
            const __nv_bfloat16* pBh = Bh + (size_t)(n0 + r_a) * K + k0 + c8a;
            const __nv_bfloat16* pBl = Bl + (size_t)(n0 + r_a) * K + k0 + c8a;
            sAh[0] = *(const uint4*)(pAh); sAh[1] = *(const uint4*)(pAh + 8);
            sAl[0] = *(const uint4*)(pAl); sAl[1] = *(const uint4*)(pAl + 8);
            sBh[0] = *(const uint4*)(pBh); sBh[1] = *(const uint4*)(pBh + 8);
            sBl[0] = *(const uint4*)(pBl); sBl[1] = *(const uint4*)(pBl + 8);
        }

        #pragma unroll
        for (int ks = 0; ks < 2; ks++){
            const int kb  = ks * 16 + ((lane & 3) << 1);  // this thread's k pair base
            const int rq  = lane >> 2;                     // quad row/col 0..7
            uint32_t bh[4][2], bl[4][2];
            #pragma unroll
            for (int nt = 0; nt < 4; nt++){
                const int n = (wn << 5) + (nt << 3) + rq;
                bh[nt][0] = *(const uint32_t*)&Bsh[n][kb];
                bh[nt][1] = *(const uint32_t*)&Bsh[n][kb + 8];
                bl[nt][0] = *(const uint32_t*)&Bsl[n][kb];
                bl[nt][1] = *(const uint32_t*)&Bsl[n][kb + 8];
            }
            #pragma unroll
            for (int mt = 0; mt < 4; mt++){
                const int r = (wm << 6) + (mt << 4) + rq;
                uint32_t ah[4], al[4];
                ah[0] = *(const uint32_t*)&Ash[r][kb];
                ah[1] = *(const uint32_t*)&Ash[r + 8][kb];
                ah[2] = *(const uint32_t*)&Ash[r][kb + 8];
                ah[3] = *(const uint32_t*)&Ash[r + 8][kb + 8];
                al[0] = *(const uint32_t*)&Asl[r][kb];
                al[1] = *(const uint32_t*)&Asl[r + 8][kb];
                al[2] = *(const uint32_t*)&Asl[r][kb + 8];
                al[3] = *(const uint32_t*)&Asl[r + 8][kb + 8];
                #pragma unroll
                for (int nt = 0; nt < 4; nt++){
                    mma16816(acc[mt][nt], ah, bh[nt]);   // Ah*Bh
                    mma16816(acc[mt][nt], al, bh[nt]);   // Al*Bh
                    mma16816(acc[mt][nt], ah, bl[nt]);   // Ah*Bl
                }
            }
        }
    }

    // epilogue: each thread owns {d0,d1} at (r,cg) and {d2,d3} at (r+8,cg)
    const int rq = lane >> 2, cg = (lane & 3) << 1;
    #pragma unroll
    for (int mt = 0; mt < 4; mt++){
        #pragma unroll
        for (int nt = 0; nt < 4; nt++){
            const int m = m0 + (wm << 6) + (mt << 4) + rq;
            const int n = n0 + (wn << 5) + (nt << 3) + cg;
            float2 d01 = make_float2(acc[mt][nt][0], acc[mt][nt][1]);
            float2 d23 = make_float2(acc[mt][nt][2], acc[mt][nt][3]);
            if (EPI == 1){
                const int bb = m >> 11, srow = m & 2047, h = n >> 6, dh = n & 63;
                float* dst = C + (((size_t)(bb * HH + h) * SS + srow) * DHH + dh);
                *(float2*)dst = d01;
                *(float2*)(dst + (size_t)8 * DHH) = d23;   // srow+8 within same head
            } else {
                const size_t off0 = (size_t)m * Nn + n;
                const size_t off1 = (size_t)(m + 8) * Nn + n;
                if (EPI == 2){
                    float2 x0 = *(const float2*)(X + off0);
                    float2 x1 = *(const float2*)(X + off1);
                    d01.x += x0.x; d01.y += x0.y;
                    d23.x += x1.x; d23.y += x1.y;
                }
                *(float2*)(C + off0) = d01;
                *(float2*)(C + off1) = d23;
            }
        }
    }
}

// ======================= weight transpose + split =======================
// W [K,N] fp32 row-major -> Th,Tl [N,K] bf16 row-major
__global__ void wt_kernel(const float* __restrict__ W,
                          __nv_bfloat16* __restrict__ Th, __nv_bfloat16* __restrict__ Tl,
                          int K, int N) {
    __shared__ float t[32][33];
    const int n0 = blockIdx.x * 32, k0 = blockIdx.y * 32;
    const int tx = threadIdx.x & 31, ty = threadIdx.x >> 5;  // 32 x 8
    #pragma unroll
    for (int i = 0; i < 32; i += 8)
        t[ty + i][tx] = W[(size_t)(k0 + ty + i) * N + n0 + tx];
    __syncthreads();
    #pragma unroll
    for (int i = 0; i < 32; i += 8){
        const float v = t[tx][ty + i];
        __nv_bfloat16 h, l;
        bf16split(v, h, l);
        const size_t o = (size_t)(n0 + ty + i) * K + k0 + tx;
        Th[o] = h; Tl[o] = l;
    }
}

// ======================= LayerNorm -> split bf16 =======================
__global__ void ln_bf16_kernel(const float* __restrict__ x,
                               const float* __restrict__ gamma,
                               const float* __restrict__ beta,
                               __nv_bfloat16* __restrict__ yh,
                               __nv_bfloat16* __restrict__ yl) {
    const int row = blockIdx.x;
    const int tid = threadIdx.x;
    const float* xr = x + (size_t)row * DD;
    float4 v = *(const float4*)(xr + tid * 4);
    float s  = v.x + v.y + v.z + v.w;
    float ss = v.x*v.x + v.y*v.y + v.z*v.z + v.w*v.w;
    #pragma unroll
    for (int off = 16; off; off >>= 1) {
        s  += __shfl_xor_sync(0xffffffffu, s,  off);
        ss += __shfl_xor_sync(0xffffffffu, ss, off);
    }
    __shared__ float sh[8], sh2[8];
    if ((tid & 31) == 0) { sh[tid >> 5] = s; sh2[tid >> 5] = ss; }
    __syncthreads();
    float tot = 0.f, tot2 = 0.f;
    #pragma unroll
    for (int i = 0; i < 8; i++) { tot += sh[i]; tot2 += sh2[i]; }
    const float mean = tot * (1.f / DD);
    const float var  = tot2 * (1.f / DD) - mean * mean;
    const float inv  = rsqrtf(var + EPSF);
    float4 g = *(const float4*)(gamma + tid * 4);
    float4 b = *(const float4*)(beta  + tid * 4);
    float o0 = g.x * (v.x - mean) * inv + b.x;
    float o1 = g.y * (v.y - mean) * inv + b.y;
    float o2 = g.z * (v.z - mean) * inv + b.z;
    float o3 = g.w * (v.w - mean) * inv + b.w;
    __align__(8) __nv_bfloat16 ho[4], lo[4];
    bf16split(o0, ho[0], lo[0]); bf16split(o1, ho[1], lo[1]);
    bf16split(o2, ho[2], lo[2]); bf16split(o3, ho[3], lo[3]);
    *(uint2*)(yh + (size_t)row * DD + tid * 4) = *(uint2*)ho;
    *(uint2*)(yl + (size_t)row * DD + tid * 4) = *(uint2*)lo;
}

// ======================= Flash attention (fp32) =======================
#define AT_PAD 68
#define ATT_SMEM (4 * 64 * AT_PAD * 4)

__global__ void attn_kernel(const float* __restrict__ Q, const float* __restrict__ K,
                            const float* __restrict__ V, const int* __restrict__ amask,
                            __nv_bfloat16* __restrict__ Oh, __nv_bfloat16* __restrict__ Ol) {
    extern __shared__ __align__(16) float sm[];
    float* Qs = sm;
    float* Ks = Qs + 64 * AT_PAD;
    float* Vs = Ks + 64 * AT_PAD;
    float* Ps = Vs + 64 * AT_PAD;
    __shared__ int mk[64];

    const int qb = blockIdx.x;
    const int bh = blockIdx.y;
    const int b  = bh >> 4;
    const int tid = threadIdx.x;
    const int tx = tid & 15, ty = tid >> 4;

    const float* Qg = Q + (size_t)bh * SS * DHH + (size_t)qb * 64 * DHH;
    const float* Kg = K + (size_t)bh * SS * DHH;
    const float* Vg = V + (size_t)bh * SS * DHH;

    for (int idx = tid; idx < 64 * 16; idx += 256) {
        const int m  = idx >> 4;
        const int d4 = (idx & 15) << 2;
        float4 v = *(const float4*)(Qg + m * DHH + d4);
        Qs[(d4 + 0) * AT_PAD + m] = v.x;
        Qs[(d4 + 1) * AT_PAD + m] = v.y;
        Qs[(d4 + 2) * AT_PAD + m] = v.z;
        Qs[(d4 + 3) * AT_PAD + m] = v.w;
    }

    float o[4][4];
    float mrow[4], lrow[4];
    #pragma unroll
    for (int i = 0; i < 4; i++) {
        mrow[i] = -1e30f; lrow[i] = 0.f;
        #pragma unroll
        for (int j = 0; j < 4; j++) o[i][j] = 0.f;
    }
    const int qrow0 = qb * 64 + ty * 4;

    for (int kb = 0; kb <= qb; kb++) {
        __syncthreads();
        for (int idx = tid; idx < 64 * 16; idx += 256) {
            const int n  = idx >> 4;
            const int d4 = (idx & 15) << 2;
            float4 kv = *(const float4*)(Kg + (size_t)(kb * 64 + n) * DHH + d4);
            Ks[(d4 + 0) * AT_PAD + n] = kv.x;
            Ks[(d4 + 1) * AT_PAD + n] = kv.y;
            Ks[(d4 + 2) * AT_PAD + n] = kv.z;
            Ks[(d4 + 3) * AT_PAD + n] = kv.w;
            float4 vv = *(const float4*)(Vg + (size_t)(kb * 64 + n) * DHH + d4);
            *(float4*)(Vs + n * AT_PAD + d4) = vv;
        }
        if (tid < 64) mk[tid] = amask[b * SS + kb * 64 + tid];
        __syncthreads();

        float s[4][4];
        #pragma unroll
        for (int i = 0; i < 4; i++)
            #pragma unroll
            for (int j = 0; j < 4; j++) s[i][j] = 0.f;
        #pragma unroll 4
        for (int k = 0; k < 64; k++) {
            float4 a4 = *(const float4*)(Qs + k * AT_PAD + (ty << 2));
            float4 b4 = *(const float4*)(Ks + k * AT_PAD + (tx << 2));
            const float ar[4] = {a4.x, a4.y, a4.z, a4.w};
            const float br[4] = {b4.x, b4.y, b4.z, b4.w};
            #pragma unroll
            for (int i = 0; i < 4; i++)
                #pragma unroll
                for (int j = 0; j < 4; j++)
                    s[i][j] += ar[i] * br[j];
        }

        #pragma unroll
        for (int i = 0; i < 4; i++) {
            const int qg = qrow0 + i;
            #pragma unroll
            for (int j = 0; j < 4; j++) {
                const int kg = kb * 64 + tx * 4 + j;
                float val = s[i][j] * 0.125f;
                if (kg > qg || mk[tx * 4 + j] == 0) val = -1e30f;
                s[i][j] = val;
            }
        }

        #pragma unroll
        for (int i = 0; i < 4; i++) {
            float rm = fmaxf(fmaxf(s[i][0], s[i][1]), fmaxf(s[i][2], s[i][3]));
            #pragma unroll
            for (int off = 8; off; off >>= 1)
                rm = fmaxf(rm, __shfl_xor_sync(0xffffffffu, rm, off));
            const float mnew  = fmaxf(mrow[i], rm);
            const float alpha = __expf(mrow[i] - mnew);
            float rs = 0.f;
            #pragma unroll
            for (int j = 0; j < 4; j++) {
                const float p = __expf(s[i][j] - mnew);
                s[i][j] = p;
                rs += p;
            }
            #pragma unroll
            for (int off = 8; off; off >>= 1)
                rs += __shfl_xor_sync(0xffffffffu, rs, off);
            lrow[i] = lrow[i] * alpha + rs;
            mrow[i] = mnew;
            #pragma unroll
            for (int j = 0; j < 4; j++) o[i][j] *= alpha;
        }

        #pragma unroll
        for (int j = 0; j < 4; j++) {
            float4 pv = make_float4(s[0][j], s[1][j], s[2][j], s[3][j]);
            *(float4*)(Ps + (tx * 4 + j) * AT_PAD + (ty << 2)) = pv;
        }
        __syncthreads();

        #pragma unroll 4
        for (int k = 0; k < 64; k++) {
            float4 p4 = *(const float4*)(Ps + k * AT_PAD + (ty << 2));
            float4 v4 = *(const float4*)(Vs + k * AT_PAD + (tx << 2));
            const float pr[4] = {p4.x, p4.y, p4.z, p4.w};
            const float vr[4] = {v4.x, v4.y, v4.z, v4.w};
            #pragma unroll
            for (int i = 0; i < 4; i++)
                #pragma unroll
                for (int j = 0; j < 4; j++)
                    o[i][j] += pr[i] * vr[j];
        }
    }

    // finalize: write split-bf16 back to [B,S,D] layout for the Wo GEMM
    const int h = bh & 15;
    #pragma unroll
    for (int i = 0; i < 4; i++) {
        const int qrow = qrow0 + i;
        const float inv = 1.f / lrow[i];
        __align__(8) __nv_bfloat16 rh[4], rl[4];
        #pragma unroll
        for (int j = 0; j < 4; j++) bf16split(o[i][j] * inv, rh[j], rl[j]);
        const size_t base = ((size_t)(b * SS + qrow)) * DD + h * DHH + tx * 4;
        *(uint2*)(Oh + base) = *(uint2*)rh;
        *(uint2*)(Ol + base) = *(uint2*)rl;
    }
}

// ======================= GLU -> split bf16 =======================
__global__ void glu_kernel(const float* __restrict__ h,
                           __nv_bfloat16* __restrict__ gh, __nv_bfloat16* __restrict__ gl) {
    const int idx = blockIdx.x * blockDim.x + threadIdx.x;
    const int r  = idx >> 9;
    const int c4 = (idx & 511) << 2;
    float4 l = *(const float4*)(h + (size_t)r * (4 * DD) + c4);
    float4 q = *(const float4*)(h + (size_t)r * (4 * DD) + 2 * DD + c4);
    float g0 = l.x / (1.f + __expf(-q.x));
    float g1 = l.y / (1.f + __expf(-q.y));
    float g2 = l.z / (1.f + __expf(-q.z));
    float g3 = l.w / (1.f + __expf(-q.w));
    __align__(8) __nv_bfloat16 hh[4], ll[4];
    bf16split(g0, hh[0], ll[0]); bf16split(g1, hh[1], ll[1]);
    bf16split(g2, hh[2], ll[2]); bf16split(g3, hh[3], ll[3]);
    *(uint2*)(gh + (size_t)r * (2 * DD) + c4) = *(uint2*)hh;
    *(uint2*)(gl + (size_t)r * (2 * DD) + c4) = *(uint2*)ll;
}

// ======================= host launcher =======================
extern "C" void kernel_launch(void* const* d_in, const int* in_sizes, int n_in,
                              void* d_out, int out_size) {
    const float* x      = (const float*)d_in[0];
    const int*   amask  = (const int*)  d_in[1];
    const float* Wq     = (const float*)d_in[2];
    const float* Wk     = (const float*)d_in[3];
    const float* Wv     = (const float*)d_in[4];
    const float* Wo     = (const float*)d_in[5];
    const float* W1     = (const float*)d_in[6];
    const float* W2     = (const float*)d_in[7];
    const float* gamma1 = (const float*)d_in[8];
    const float* beta1  = (const float*)d_in[9];
    const float* gamma2 = (const float*)d_in[10];
    const float* beta2  = (const float*)d_in[11];
    float* out = (float*)d_out;

    float *p_q, *p_k, *p_v, *p_x1, *p_h;
    __nv_bfloat16 *p_a1h, *p_a1l, *p_ath, *p_atl, *p_l2h, *p_l2l, *p_gh, *p_gl;
    __nv_bfloat16 *p_wqh, *p_wql, *p_wkh, *p_wkl, *p_wvh, *p_wvl, *p_woh, *p_wol;
    __nv_bfloat16 *p_w1h, *p_w1l, *p_w2h, *p_w2l;
    cudaGetSymbolAddress((void**)&p_q,   g_q);
    cudaGetSymbolAddress((void**)&p_k,   g_k);
    cudaGetSymbolAddress((void**)&p_v,   g_v);
    cudaGetSymbolAddress((void**)&p_x1,  g_x1);
    cudaGetSymbolAddress((void**)&p_h,   g_h);
    cudaGetSymbolAddress((void**)&p_a1h, g_a1h); cudaGetSymbolAddress((void**)&p_a1l, g_a1l);
    cudaGetSymbolAddress((void**)&p_ath, g_ath); cudaGetSymbolAddress((void**)&p_atl, g_atl);
    cudaGetSymbolAddress((void**)&p_l2h, g_l2h); cudaGetSymbolAddress((void**)&p_l2l, g_l2l);
    cudaGetSymbolAddress((void**)&p_gh,  g_gh);  cudaGetSymbolAddress((void**)&p_gl,  g_gl);
    cudaGetSymbolAddress((void**)&p_wqh, g_wqh); cudaGetSymbolAddress((void**)&p_wql, g_wql);
    cudaGetSymbolAddress((void**)&p_wkh, g_wkh); cudaGetSymbolAddress((void**)&p_wkl, g_wkl);
    cudaGetSymbolAddress((void**)&p_wvh, g_wvh); cudaGetSymbolAddress((void**)&p_wvl, g_wvl);
    cudaGetSymbolAddress((void**)&p_woh, g_woh); cudaGetSymbolAddress((void**)&p_wol, g_wol);
    cudaGetSymbolAddress((void**)&p_w1h, g_w1h); cudaGetSymbolAddress((void**)&p_w1l, g_w1l);
    cudaGetSymbolAddress((void**)&p_w2h, g_w2h); cudaGetSymbolAddress((void**)&p_w2l, g_w2l);

    cudaFuncSetAttribute(attn_kernel, cudaFuncAttributeMaxDynamicSharedMemorySize, ATT_SMEM);

    // 0. weight transpose + split (W [K,N] -> [N,K] hi/lo bf16)
    wt_kernel<<<dim3(DD/32,   DD/32),   256>>>(Wq, p_wqh, p_wql, DD,   DD);
    wt_kernel<<<dim3(DD/32,   DD/32),   256>>>(Wk, p_wkh, p_wkl, DD,   DD);
    wt_kernel<<<dim3(DD/32,   DD/32),   256>>>(Wv, p_wvh, p_wvl, DD,   DD);
    wt_kernel<<<dim3(DD/32,   DD/32),   256>>>(Wo, p_woh, p_wol, DD,   DD);
    wt_kernel<<<dim3(4*DD/32, DD/32),   256>>>(W1, p_w1h, p_w1l, DD,   4*DD);
    wt_kernel<<<dim3(DD/32,   2*DD/32), 256>>>(W2, p_w2h, p_w2l, 2*DD, DD);

    // 1. ln1 -> split bf16
    ln_bf16_kernel<<<ROWS, 256>>>(x, gamma1, beta1, p_a1h, p_a1l);
    // 2. QKV projections (mma.sync, head-scatter fp32 epilogue)
    mma_gemm<1><<<dim3(8, 32), 256>>>(p_a1h, p_a1l, p_wqh, p_wql, p_q, nullptr, DD, DD);
    mma_gemm<1><<<dim3(8, 32), 256>>>(p_a1h, p_a1l, p_wkh, p_wkl, p_k, nullptr, DD, DD);
    mma_gemm<1><<<dim3(8, 32), 256>>>(p_a1h, p_a1l, p_wvh, p_wvl, p_v, nullptr, DD, DD);
    // 3. causal flash attention (fp32) -> split bf16
    attn_kernel<<<dim3(SS/64, BB*HH), 256, ATT_SMEM>>>(p_q, p_k, p_v, amask, p_ath, p_atl);
    // 4. Wo + residual -> x1
    mma_gemm<2><<<dim3(8, 32), 256>>>(p_ath, p_atl, p_woh, p_wol, p_x1, x, DD, DD);
    // 5. ln2 -> split bf16
    ln_bf16_kernel<<<ROWS, 256>>>(p_x1, gamma2, beta2, p_l2h, p_l2l);
    // 6. W1 (D -> 4D)
    mma_gemm<0><<<dim3(32, 32), 256>>>(p_l2h, p_l2l, p_w1h, p_w1l, p_h, nullptr, 4*DD, DD);
    // 7. GLU -> split bf16
    glu_kernel<<<(ROWS * 2 * DD / 4) / 256, 256>>>(p_h, p_gh, p_gl);
    // 8. W2 + residual -> out
    mma_gemm<2><<<dim3(8, 32), 256>>>(p_gh, p_gl, p_w2h, p_w2l, out, p_x1, DD, 2*DD);
}

// round 9
// speedup vs baseline: 2.0465x; 1.3492x over previous
#include <cuda_runtime.h>
#include <cuda_bf16.h>
#include <cstdint>
#include <math.h>

// Problem constants
#define BB 2
#define SS 2048
#define DD 1024
#define HH 16
#define DHH 64
#define ROWS (BB*SS)        // 4096
#define EPSF 1e-5f

// ======================= scratch (device globals) =======================
__device__ float g_x1  [(size_t)ROWS*DD];
__device__ float g_h   [(size_t)ROWS*4*DD];

// split-bf16 activations (hi/lo)
__device__ __nv_bfloat16 g_a1h[(size_t)ROWS*DD],   g_a1l[(size_t)ROWS*DD];
__device__ __nv_bfloat16 g_ath[(size_t)ROWS*DD],   g_atl[(size_t)ROWS*DD];
__device__ __nv_bfloat16 g_l2h[(size_t)ROWS*DD],   g_l2l[(size_t)ROWS*DD];
__device__ __nv_bfloat16 g_gh [(size_t)ROWS*2*DD], g_gl [(size_t)ROWS*2*DD];

// split-bf16 Q/K head-layout [bh][s][dh], V transposed [bh][dh][s]
__device__ __nv_bfloat16 g_qh [(size_t)ROWS*DD], g_ql [(size_t)ROWS*DD];
__device__ __nv_bfloat16 g_kh [(size_t)ROWS*DD], g_kl [(size_t)ROWS*DD];
__device__ __nv_bfloat16 g_vth[(size_t)ROWS*DD], g_vtl[(size_t)ROWS*DD];

// transposed split-bf16 weights: [N, K] K-major
__device__ __nv_bfloat16 g_wqh[(size_t)DD*DD], g_wql[(size_t)DD*DD];
__device__ __nv_bfloat16 g_wkh[(size_t)DD*DD], g_wkl[(size_t)DD*DD];
__device__ __nv_bfloat16 g_wvh[(size_t)DD*DD], g_wvl[(size_t)DD*DD];
__device__ __nv_bfloat16 g_woh[(size_t)DD*DD], g_wol[(size_t)DD*DD];
__device__ __nv_bfloat16 g_w1h[(size_t)DD*4*DD], g_w1l[(size_t)DD*4*DD];
__device__ __nv_bfloat16 g_w2h[(size_t)2*DD*DD], g_w2l[(size_t)2*DD*DD];

__device__ __forceinline__ void bf16split(float v, __nv_bfloat16& h, __nv_bfloat16& l){
    h = __float2bfloat16(v);
    l = __float2bfloat16(v - __bfloat162float(h));
}
// split a float pair into packed bf16x2 hi/lo words (low half = first elem)
__device__ __forceinline__ void split2(float a, float b, uint32_t& hi, uint32_t& lo){
    __nv_bfloat16 ha = __float2bfloat16(a), hb = __float2bfloat16(b);
    float ra = a - __bfloat162float(ha), rb = b - __bfloat162float(hb);
    __nv_bfloat16 la = __float2bfloat16(ra), lb = __float2bfloat16(rb);
    hi = ((uint32_t)__bfloat16_as_ushort(hb) << 16) | (uint32_t)__bfloat16_as_ushort(ha);
    lo = ((uint32_t)__bfloat16_as_ushort(lb) << 16) | (uint32_t)__bfloat16_as_ushort(la);
}

// m16n8k16 bf16 MMA, fp32 accumulate (baseline PTX, works on non-'a' targets)
__device__ __forceinline__ void mma16816(float* c, const uint32_t* a, const uint32_t* b){
    asm volatile(
        "mma.sync.aligned.m16n8k16.row.col.f32.bf16.bf16.f32 "
        "{%0,%1,%2,%3}, {%4,%5,%6,%7}, {%8,%9}, {%0,%1,%2,%3};"
        : "+f"(c[0]), "+f"(c[1]), "+f"(c[2]), "+f"(c[3])
        : "r"(a[0]), "r"(a[1]), "r"(a[2]), "r"(a[3]), "r"(b[0]), "r"(b[1]));
}

// ======================= split-bf16 MMA GEMM =======================
// C[M,Nn] = (Ah+Al)[M,K] @ (Bh+Bl)[Nn,K]^T   (B pre-transposed, K-major)
// EPI 0: plain fp32 C
// EPI 2: fp32 C = acc + X
// EPI 3: split-bf16 head layout [bh][s][dh] -> CH/CL
// EPI 4: split-bf16 transposed head layout [bh][dh][s] -> CH/CL
#define KC 32
#define APAD 40

template<int EPI>
__global__ __launch_bounds__(256)
void mma_gemm(const __nv_bfloat16* __restrict__ Ah, const __nv_bfloat16* __restrict__ Al,
              const __nv_bfloat16* __restrict__ Bh, const __nv_bfloat16* __restrict__ Bl,
              float* __restrict__ C, const float* __restrict__ X,
              __nv_bfloat16* __restrict__ CH, __nv_bfloat16* __restrict__ CL,
              int Nn, int K) {
    __shared__ __align__(16) __nv_bfloat16 Ash[128][APAD], Asl[128][APAD];
    __shared__ __align__(16) __nv_bfloat16 Bsh[128][APAD], Bsl[128][APAD];

    const int tid  = threadIdx.x;
    const int wid  = tid >> 5, lane = tid & 31;
    const int wm   = wid & 1, wn = wid >> 1;       // warp grid 2(m) x 4(n)
    const int m0   = blockIdx.y << 7, n0 = blockIdx.x << 7;

    const int r_a  = tid >> 1;
    const int c8a  = (tid & 1) << 4;

    float acc[4][4][4];
    #pragma unroll
    for (int mt = 0; mt < 4; mt++)
        #pragma unroll
        for (int nt = 0; nt < 4; nt++)
            #pragma unroll
            for (int j = 0; j < 4; j++) acc[mt][nt][j] = 0.f;

    const int nc = K / KC;
    uint4 sAh[2], sAl[2], sBh[2], sBl[2];

    {
        const __nv_bfloat16* pAh = Ah + (size_t)(m0 + r_a) * K + c8a;
        const __nv_bfloat16* pAl = Al + (size_t)(m0 + r_a) * K + c8a;
        const __nv_bfloat16* pBh = Bh + (size_t)(n0 + r_a) * K + c8a;
        const __nv_bfloat16* pBl = Bl + (size_t)(n0 + r_a) * K + c8a;
        sAh[0] = *(const uint4*)(pAh);     sAh[1] = *(const uint4*)(pAh + 8);
        sAl[0] = *(const uint4*)(pAl);     sAl[1] = *(const uint4*)(pAl + 8);
        sBh[0] = *(const uint4*)(pBh);     sBh[1] = *(const uint4*)(pBh + 8);
        sBl[0] = *(const uint4*)(pBl);     sBl[1] = *(const uint4*)(pBl + 8);
    }

    for (int kc = 0; kc < nc; kc++){
        __syncthreads();
        *(uint4*)&Ash[r_a][c8a]     = sAh[0];  *(uint4*)&Ash[r_a][c8a + 8] = sAh[1];
        *(uint4*)&Asl[r_a][c8a]     = sAl[0];  *(uint4*)&Asl[r_a][c8a + 8] = sAl[1];
        *(uint4*)&Bsh[r_a][c8a]     = sBh[0];  *(uint4*)&Bsh[r_a][c8a + 8] = sBh[1];
        *(uint4*)&Bsl[r_a][c8a]     = sBl[0];  *(uint4*)&Bsl[r_a][c8a + 8] = sBl[1];
        __syncthreads();

        if (kc + 1 < nc){
            const int k0 = (kc + 1) * KC;
            const __nv_bfloat16* pAh = Ah + (size_t)(m0 + r_a) * K + k0 + c8a;
            const __nv_bfloat16* pAl = Al + (size_t)(m0 + r_a) * K + k0 + c8a;
            const __nv_bfloat16* pBh = Bh + (size_t)(n0 + r_a) * K + k0 + c8a;
            const __nv_bfloat16* pBl = Bl + (size_t)(n0 + r_a) * K + k0 + c8a;
            sAh[0] = *(const uint4*)(pAh); sAh[1] = *(const uint4*)(pAh + 8);
            sAl[0] = *(const uint4*)(pAl); sAl[1] = *(const uint4*)(pAl + 8);
            sBh[0] = *(const uint4*)(pBh); sBh[1] = *(const uint4*)(pBh + 8);
            sBl[0] = *(const uint4*)(pBl); sBl[1] = *(const uint4*)(pBl + 8);
        }

        #pragma unroll
        for (int ks = 0; ks < 2; ks++){
            const int kb  = ks * 16 + ((lane & 3) << 1);
            const int rq  = lane >> 2;
            uint32_t bh[4][2], bl[4][2];
            #pragma unroll
            for (int nt = 0; nt < 4; nt++){
                const int n = (wn << 5) + (nt << 3) + rq;
                bh[nt][0] = *(const uint32_t*)&Bsh[n][kb];
                bh[nt][1] = *(const uint32_t*)&Bsh[n][kb + 8];
                bl[nt][0] = *(const uint32_t*)&Bsl[n][kb];
                bl[nt][1] = *(const uint32_t*)&Bsl[n][kb + 8];
            }
            #pragma unroll
            for (int mt = 0; mt < 4; mt++){
                const int r = (wm << 6) + (mt << 4) + rq;
                uint32_t ah[4], al[4];
                ah[0] = *(const uint32_t*)&Ash[r][kb];
                ah[1] = *(const uint32_t*)&Ash[r + 8][kb];
                ah[2] = *(const uint32_t*)&Ash[r][kb + 8];
                ah[3] = *(const uint32_t*)&Ash[r + 8][kb + 8];
                al[0] = *(const uint32_t*)&Asl[r][kb];
                al[1] = *(const uint32_t*)&Asl[r + 8][kb];
                al[2] = *(const uint32_t*)&Asl[r][kb + 8];
                al[3] = *(const uint32_t*)&Asl[r + 8][kb + 8];
                #pragma unroll
                for (int nt = 0; nt < 4; nt++){
                    mma16816(acc[mt][nt], ah, bh[nt]);   // Ah*Bh
                    mma16816(acc[mt][nt], al, bh[nt]);   // Al*Bh
                    mma16816(acc[mt][nt], ah, bl[nt]);   // Ah*Bl
                }
            }
        }
    }

    const int rq = lane >> 2, cg = (lane & 3) << 1;
    #pragma unroll
    for (int mt = 0; mt < 4; mt++){
        #pragma unroll
        for (int nt = 0; nt < 4; nt++){
            const int m = m0 + (wm << 6) + (mt << 4) + rq;
            const int n = n0 + (wn << 5) + (nt << 3) + cg;
            float2 d01 = make_float2(acc[mt][nt][0], acc[mt][nt][1]);
            float2 d23 = make_float2(acc[mt][nt][2], acc[mt][nt][3]);
            if (EPI == 3){
                const int bb2 = m >> 11, srow = m & 2047, hh2 = n >> 6, dh = n & 63;
                const size_t base = ((size_t)(bb2 * HH + hh2) * SS + srow) * DHH + dh;
                uint32_t h0, l0, h1, l1;
                split2(d01.x, d01.y, h0, l0);
                split2(d23.x, d23.y, h1, l1);
                *(uint32_t*)(CH + base)            = h0;
                *(uint32_t*)(CL + base)            = l0;
                *(uint32_t*)(CH + base + 8 * DHH)  = h1;
                *(uint32_t*)(CL + base + 8 * DHH)  = l1;
            } else if (EPI == 4){
                const int bb2 = m >> 11, srow = m & 2047, hh2 = n >> 6, dh = n & 63;
                const size_t base = ((size_t)(bb2 * HH + hh2) * DHH + dh) * SS + srow;
                __nv_bfloat16 hq, lq;
                bf16split(d01.x, hq, lq); CH[base]          = hq; CL[base]          = lq;
                bf16split(d01.y, hq, lq); CH[base + SS]     = hq; CL[base + SS]     = lq;
                bf16split(d23.x, hq, lq); CH[base + 8]      = hq; CL[base + 8]      = lq;
                bf16split(d23.y, hq, lq); CH[base + SS + 8] = hq; CL[base + SS + 8] = lq;
            } else {
                const size_t off0 = (size_t)m * Nn + n;
                const size_t off1 = (size_t)(m + 8) * Nn + n;
                if (EPI == 2){
                    float2 x0 = *(const float2*)(X + off0);
                    float2 x1 = *(const float2*)(X + off1);
                    d01.x += x0.x; d01.y += x0.y;
                    d23.x += x1.x; d23.y += x1.y;
                }
                *(float2*)(C + off0) = d01;
                *(float2*)(C + off1) = d23;
            }
        }
    }
}

// ======================= weight transpose + split =======================
__global__ void wt_kernel(const float* __restrict__ W,
                          __nv_bfloat16* __restrict__ Th, __nv_bfloat16* __restrict__ Tl,
                          int K, int N) {
    __shared__ float t[32][33];
    const int n0 = blockIdx.x * 32, k0 = blockIdx.y * 32;
    const int tx = threadIdx.x & 31, ty = threadIdx.x >> 5;
    #pragma unroll
    for (int i = 0; i < 32; i += 8)
        t[ty + i][tx] = W[(size_t)(k0 + ty + i) * N + n0 + tx];
    __syncthreads();
    #pragma unroll
    for (int i = 0; i < 32; i += 8){
        const float v = t[tx][ty + i];
        __nv_bfloat16 h, l;
        bf16split(v, h, l);
        const size_t o = (size_t)(n0 + ty + i) * K + k0 + tx;
        Th[o] = h; Tl[o] = l;
    }
}

// ======================= LayerNorm -> split bf16 =======================
__global__ void ln_bf16_kernel(const float* __restrict__ x,
                               const float* __restrict__ gamma,
                               const float* __restrict__ beta,
                               __nv_bfloat16* __restrict__ yh,
                               __nv_bfloat16* __restrict__ yl) {
    const int row = blockIdx.x;
    const int tid = threadIdx.x;
    const float* xr = x + (size_t)row * DD;
    float4 v = *(const float4*)(xr + tid * 4);
    float s  = v.x + v.y + v.z + v.w;
    float ss = v.x*v.x + v.y*v.y + v.z*v.z + v.w*v.w;
    #pragma unroll
    for (int off = 16; off; off >>= 1) {
        s  += __shfl_xor_sync(0xffffffffu, s,  off);
        ss += __shfl_xor_sync(0xffffffffu, ss, off);
    }
    __shared__ float sh[8], sh2[8];
    if ((tid & 31) == 0) { sh[tid >> 5] = s; sh2[tid >> 5] = ss; }
    __syncthreads();
    float tot = 0.f, tot2 = 0.f;
    #pragma unroll
    for (int i = 0; i < 8; i++) { tot += sh[i]; tot2 += sh2[i]; }
    const float mean = tot * (1.f / DD);
    const float var  = tot2 * (1.f / DD) - mean * mean;
    const float inv  = rsqrtf(var + EPSF);
    float4 g = *(const float4*)(gamma + tid * 4);
    float4 b = *(const float4*)(beta  + tid * 4);
    float o0 = g.x * (v.x - mean) * inv + b.x;
    float o1 = g.y * (v.y - mean) * inv + b.y;
    float o2 = g.z * (v.z - mean) * inv + b.z;
    float o3 = g.w * (v.w - mean) * inv + b.w;
    uint32_t h0, l0, h1, l1;
    split2(o0, o1, h0, l0);
    split2(o2, o3, h1, l1);
    uint2 ph = make_uint2(h0, h1), pl = make_uint2(l0, l1);
    *(uint2*)(yh + (size_t)row * DD + tid * 4) = ph;
    *(uint2*)(yl + (size_t)row * DD + tid * 4) = pl;
}

// ======================= tensor-core flash attention =======================
// 128 threads / 4 warps, 64-query tile. Split-bf16 3-pass for both QK and PV.
// Q/K global: [bh][s][dh] split bf16.  V global: [bh][dh][s] split bf16 (transposed).
#define DP 72
#define ATT2_SMEM (6 * 64 * DP * 2)

__global__ __launch_bounds__(128)
void attn_mma(const __nv_bfloat16* __restrict__ Qh_, const __nv_bfloat16* __restrict__ Ql_,
              const __nv_bfloat16* __restrict__ Kh_, const __nv_bfloat16* __restrict__ Kl_,
              const __nv_bfloat16* __restrict__ Vth_, const __nv_bfloat16* __restrict__ Vtl_,
              const int* __restrict__ amask,
              __nv_bfloat16* __restrict__ Oh, __nv_bfloat16* __restrict__ Ol) {
    extern __shared__ __align__(16) __nv_bfloat16 smx[];
    __nv_bfloat16* Qsh = smx;
    __nv_bfloat16* Qsl = Qsh + 64 * DP;
    __nv_bfloat16* Ksh = Qsl + 64 * DP;
    __nv_bfloat16* Ksl = Ksh + 64 * DP;
    __nv_bfloat16* Vsh = Ksl + 64 * DP;   // [dh][key]
    __nv_bfloat16* Vsl = Vsh + 64 * DP;
    __shared__ int mk[64];

    const int qb = blockIdx.x, bh = blockIdx.y, b = bh >> 4, h = bh & 15;
    const int tid = threadIdx.x, lane = tid & 31, w = tid >> 5;
    const int rq = lane >> 2, t2 = (lane & 3) << 1;

    // stage Q tile once
    {
        const __nv_bfloat16* gh = Qh_ + ((size_t)bh * SS + qb * 64) * DHH;
        const __nv_bfloat16* gl = Ql_ + ((size_t)bh * SS + qb * 64) * DHH;
        for (int idx = tid; idx < 64 * 8; idx += 128) {
            const int r = idx >> 3, sg = (idx & 7) << 3;
            *(uint4*)&Qsh[r * DP + sg] = *(const uint4*)(gh + r * DHH + sg);
            *(uint4*)&Qsl[r * DP + sg] = *(const uint4*)(gl + r * DHH + sg);
        }
    }

    float o[8][4];
    #pragma unroll
    for (int i = 0; i < 8; i++) { o[i][0] = o[i][1] = o[i][2] = o[i][3] = 0.f; }
    float m0 = -1e30f, m1 = -1e30f, l0 = 0.f, l1 = 0.f;
    const int rg0 = qb * 64 + (w << 4) + rq;   // global query row (first of pair)

    for (int kb = 0; kb <= qb; kb++) {
        __syncthreads();
        {
            const __nv_bfloat16* gh = Kh_  + ((size_t)bh * SS + kb * 64) * DHH;
            const __nv_bfloat16* gl = Kl_  + ((size_t)bh * SS + kb * 64) * DHH;
            const __nv_bfloat16* vh = Vth_ + ((size_t)bh * DHH) * SS + kb * 64;
            const __nv_bfloat16* vl = Vtl_ + ((size_t)bh * DHH) * SS + kb * 64;
            for (int idx = tid; idx < 64 * 8; idx += 128) {
                const int r = idx >> 3, sg = (idx & 7) << 3;
                *(uint4*)&Ksh[r * DP + sg] = *(const uint4*)(gh + r * DHH + sg);
                *(uint4*)&Ksl[r * DP + sg] = *(const uint4*)(gl + r * DHH + sg);
                *(uint4*)&Vsh[r * DP + sg] = *(const uint4*)(vh + (size_t)r * SS + sg);
                *(uint4*)&Vsl[r * DP + sg] = *(const uint4*)(vl + (size_t)r * SS + sg);
            }
            if (tid < 64) mk[tid] = amask[b * SS + kb * 64 + tid];
        }
        __syncthreads();

        // S = (Qh+Ql) @ (Kh+Kl)^T  (3-pass)
        float s[8][4];
        #pragma unroll
        for (int i = 0; i < 8; i++) { s[i][0] = s[i][1] = s[i][2] = s[i][3] = 0.f; }
        #pragma unroll
        for (int k16 = 0; k16 < 4; k16++) {
            const int ar = (w << 4) + rq;
            const int ac = t2 + (k16 << 4);
            uint32_t ah4[4], al4[4];
            ah4[0] = *(const uint32_t*)&Qsh[ar * DP + ac];
            ah4[1] = *(const uint32_t*)&Qsh[(ar + 8) * DP + ac];
            ah4[2] = *(const uint32_t*)&Qsh[ar * DP + ac + 8];
            ah4[3] = *(const uint32_t*)&Qsh[(ar + 8) * DP + ac + 8];
            al4[0] = *(const uint32_t*)&Qsl[ar * DP + ac];
            al4[1] = *(const uint32_t*)&Qsl[(ar + 8) * DP + ac];
            al4[2] = *(const uint32_t*)&Qsl[ar * DP + ac + 8];
            al4[3] = *(const uint32_t*)&Qsl[(ar + 8) * DP + ac + 8];
            #pragma unroll
            for (int n8 = 0; n8 < 8; n8++) {
                const int br = (n8 << 3) + rq;
                uint32_t bh2[2], bl2[2];
                bh2[0] = *(const uint32_t*)&Ksh[br * DP + ac];
                bh2[1] = *(const uint32_t*)&Ksh[br * DP + ac + 8];
                bl2[0] = *(const uint32_t*)&Ksl[br * DP + ac];
                bl2[1] = *(const uint32_t*)&Ksl[br * DP + ac + 8];
                mma16816(s[n8], ah4, bh2);
                mma16816(s[n8], al4, bh2);
                mma16816(s[n8], ah4, bl2);
            }
        }

        // scale + mask + online softmax (rows r and r+8)
        const bool diag = (kb == qb);
        float rm0 = -1e30f, rm1 = -1e30f;
        #pragma unroll
        for (int n8 = 0; n8 < 8; n8++) {
            const int c0 = (n8 << 3) + t2;
            #pragma unroll
            for (int v = 0; v < 2; v++) {
                const int c = c0 + v;
                const int cgl = kb * 64 + c;
                float x0 = s[n8][v] * 0.125f;
                float x1 = s[n8][2 + v] * 0.125f;
                const bool km = (mk[c] != 0);
                if (!km || (diag && cgl > rg0))     x0 = -1e30f;
                if (!km || (diag && cgl > rg0 + 8)) x1 = -1e30f;
                s[n8][v] = x0; s[n8][2 + v] = x1;
                rm0 = fmaxf(rm0, x0); rm1 = fmaxf(rm1, x1);
            }
        }
        rm0 = fmaxf(rm0, __shfl_xor_sync(0xffffffffu, rm0, 1));
        rm0 = fmaxf(rm0, __shfl_xor_sync(0xffffffffu, rm0, 2));
        rm1 = fmaxf(rm1, __shfl_xor_sync(0xffffffffu, rm1, 1));
        rm1 = fmaxf(rm1, __shfl_xor_sync(0xffffffffu, rm1, 2));
        const float mn0 = fmaxf(m0, rm0), mn1 = fmaxf(m1, rm1);
        const float a0 = __expf(m0 - mn0), a1 = __expf(m1 - mn1);
        float rs0 = 0.f, rs1 = 0.f;
        #pragma unroll
        for (int n8 = 0; n8 < 8; n8++) {
            #pragma unroll
            for (int v = 0; v < 2; v++) {
                float p0 = __expf(s[n8][v] - mn0);
                float p1 = __expf(s[n8][2 + v] - mn1);
                s[n8][v] = p0; s[n8][2 + v] = p1;
                rs0 += p0; rs1 += p1;
            }
        }
        rs0 += __shfl_xor_sync(0xffffffffu, rs0, 1);
        rs0 += __shfl_xor_sync(0xffffffffu, rs0, 2);
        rs1 += __shfl_xor_sync(0xffffffffu, rs1, 1);
        rs1 += __shfl_xor_sync(0xffffffffu, rs1, 2);
        l0 = l0 * a0 + rs0; l1 = l1 * a1 + rs1;
        m0 = mn0; m1 = mn1;
        #pragma unroll
        for (int n8 = 0; n8 < 8; n8++) {
            o[n8][0] *= a0; o[n8][1] *= a0; o[n8][2] *= a1; o[n8][3] *= a1;
        }

        // repack P (C layout) -> A fragments (split bf16), in registers
        uint32_t Ph[4][4], Pl[4][4];
        #pragma unroll
        for (int jj = 0; jj < 4; jj++) {
            const int j0 = jj << 1, j1 = j0 + 1;
            split2(s[j0][0], s[j0][1], Ph[jj][0], Pl[jj][0]);
            split2(s[j0][2], s[j0][3], Ph[jj][1], Pl[jj][1]);
            split2(s[j1][0], s[j1][1], Ph[jj][2], Pl[jj][2]);
            split2(s[j1][2], s[j1][3], Ph[jj][3], Pl[jj][3]);
        }

        // O += (Ph+Pl) @ (Vh+Vl)   (V stored [dh][key] = B operand col-major)
        #pragma unroll
        for (int jj = 0; jj < 4; jj++) {
            const int kc = t2 + (jj << 4);
            #pragma unroll
            for (int n8 = 0; n8 < 8; n8++) {
                const int vr = (n8 << 3) + rq;
                uint32_t vh2[2], vl2[2];
                vh2[0] = *(const uint32_t*)&Vsh[vr * DP + kc];
                vh2[1] = *(const uint32_t*)&Vsh[vr * DP + kc + 8];
                vl2[0] = *(const uint32_t*)&Vsl[vr * DP + kc];
                vl2[1] = *(const uint32_t*)&Vsl[vr * DP + kc + 8];
                mma16816(o[n8], Ph[jj], vh2);
                mma16816(o[n8], Pl[jj], vh2);
                mma16816(o[n8], Ph[jj], vl2);
            }
        }
    }

    // finalize -> split bf16 [B,S,D]
    const float i0 = 1.f / l0, i1 = 1.f / l1;
    const size_t row0 = (size_t)(b * SS) + qb * 64 + (w << 4) + rq;
    #pragma unroll
    for (int n8 = 0; n8 < 8; n8++) {
        const int col = h * DHH + (n8 << 3) + t2;
        uint32_t hh0, ll0, hh1, ll1;
        split2(o[n8][0] * i0, o[n8][1] * i0, hh0, ll0);
        split2(o[n8][2] * i1, o[n8][3] * i1, hh1, ll1);
        *(uint32_t*)(Oh + row0 * DD + col)       = hh0;
        *(uint32_t*)(Ol + row0 * DD + col)       = ll0;
        *(uint32_t*)(Oh + (row0 + 8) * DD + col) = hh1;
        *(uint32_t*)(Ol + (row0 + 8) * DD + col) = ll1;
    }
}

// ======================= GLU -> split bf16 =======================
__global__ void glu_kernel(const float* __restrict__ h,
                           __nv_bfloat16* __restrict__ gh, __nv_bfloat16* __restrict__ gl) {
    const int idx = blockIdx.x * blockDim.x + threadIdx.x;
    const int r  = idx >> 9;
    const int c4 = (idx & 511) << 2;
    float4 l = *(const float4*)(h + (size_t)r * (4 * DD) + c4);
    float4 q = *(const float4*)(h + (size_t)r * (4 * DD) + 2 * DD + c4);
    float g0 = l.x / (1.f + __expf(-q.x));
    float g1 = l.y / (1.f + __expf(-q.y));
    float g2 = l.z / (1.f + __expf(-q.z));
    float g3 = l.w / (1.f + __expf(-q.w));
    uint32_t h0, l0, h1, l1;
    split2(g0, g1, h0, l0);
    split2(g2, g3, h1, l1);
    uint2 ph = make_uint2(h0, h1), pl = make_uint2(l0, l1);
    *(uint2*)(gh + (size_t)r * (2 * DD) + c4) = ph;
    *(uint2*)(gl + (size_t)r * (2 * DD) + c4) = pl;
}

// ======================= host launcher =======================
extern "C" void kernel_launch(void* const* d_in, const int* in_sizes, int n_in,
                              void* d_out, int out_size) {
    const float* x      = (const float*)d_in[0];
    const int*   amask  = (const int*)  d_in[1];
    const float* Wq     = (const float*)d_in[2];
    const float* Wk     = (const float*)d_in[3];
    const float* Wv     = (const float*)d_in[4];
    const float* Wo     = (const float*)d_in[5];
    const float* W1     = (const float*)d_in[6];
    const float* W2     = (const float*)d_in[7];
    const float* gamma1 = (const float*)d_in[8];
    const float* beta1  = (const float*)d_in[9];
    const float* gamma2 = (const float*)d_in[10];
    const float* beta2  = (const float*)d_in[11];
    float* out = (float*)d_out;

    float *p_x1, *p_h;
    __nv_bfloat16 *p_a1h, *p_a1l, *p_ath, *p_atl, *p_l2h, *p_l2l, *p_gh, *p_gl;
    __nv_bfloat16 *p_qh, *p_ql, *p_kh, *p_kl, *p_vth, *p_vtl;
    __nv_bfloat16 *p_wqh, *p_wql, *p_wkh, *p_wkl, *p_wvh, *p_wvl, *p_woh, *p_wol;
    __nv_bfloat16 *p_w1h, *p_w1l, *p_w2h, *p_w2l;
    cudaGetSymbolAddress((void**)&p_x1,  g_x1);
    cudaGetSymbolAddress((void**)&p_h,   g_h);
    cudaGetSymbolAddress((void**)&p_a1h, g_a1h); cudaGetSymbolAddress((void**)&p_a1l, g_a1l);
    cudaGetSymbolAddress((void**)&p_ath, g_ath); cudaGetSymbolAddress((void**)&p_atl, g_atl);
    cudaGetSymbolAddress((void**)&p_l2h, g_l2h); cudaGetSymbolAddress((void**)&p_l2l, g_l2l);
    cudaGetSymbolAddress((void**)&p_gh,  g_gh);  cudaGetSymbolAddress((void**)&p_gl,  g_gl);
    cudaGetSymbolAddress((void**)&p_qh,  g_qh);  cudaGetSymbolAddress((void**)&p_ql,  g_ql);
    cudaGetSymbolAddress((void**)&p_kh,  g_kh);  cudaGetSymbolAddress((void**)&p_kl,  g_kl);
    cudaGetSymbolAddress((void**)&p_vth, g_vth); cudaGetSymbolAddress((void**)&p_vtl, g_vtl);
    cudaGetSymbolAddress((void**)&p_wqh, g_wqh); cudaGetSymbolAddress((void**)&p_wql, g_wql);
    cudaGetSymbolAddress((void**)&p_wkh, g_wkh); cudaGetSymbolAddress((void**)&p_wkl, g_wkl);
    cudaGetSymbolAddress((void**)&p_wvh, g_wvh); cudaGetSymbolAddress((void**)&p_wvl, g_wvl);
    cudaGetSymbolAddress((void**)&p_woh, g_woh); cudaGetSymbolAddress((void**)&p_wol, g_wol);
    cudaGetSymbolAddress((void**)&p_w1h, g_w1h); cudaGetSymbolAddress((void**)&p_w1l, g_w1l);
    cudaGetSymbolAddress((void**)&p_w2h, g_w2h); cudaGetSymbolAddress((void**)&p_w2l, g_w2l);

    cudaFuncSetAttribute(attn_mma, cudaFuncAttributeMaxDynamicSharedMemorySize, ATT2_SMEM);

    // 0. weight transpose + split
    wt_kernel<<<dim3(DD/32,   DD/32),   256>>>(Wq, p_wqh, p_wql, DD,   DD);
    wt_kernel<<<dim3(DD/32,   DD/32),   256>>>(Wk, p_wkh, p_wkl, DD,   DD);
    wt_kernel<<<dim3(DD/32,   DD/32),   256>>>(Wv, p_wvh, p_wvl, DD,   DD);
    wt_kernel<<<dim3(DD/32,   DD/32),   256>>>(Wo, p_woh, p_wol, DD,   DD);
    wt_kernel<<<dim3(4*DD/32, DD/32),   256>>>(W1, p_w1h, p_w1l, DD,   4*DD);
    wt_kernel<<<dim3(DD/32,   2*DD/32), 256>>>(W2, p_w2h, p_w2l, 2*DD, DD);

    // 1. ln1 -> split bf16
    ln_bf16_kernel<<<ROWS, 256>>>(x, gamma1, beta1, p_a1h, p_a1l);
    // 2. QKV projections -> split bf16 (Q,K head layout; V transposed)
    mma_gemm<3><<<dim3(8, 32), 256>>>(p_a1h, p_a1l, p_wqh, p_wql, nullptr, nullptr, p_qh,  p_ql,  DD, DD);
    mma_gemm<3><<<dim3(8, 32), 256>>>(p_a1h, p_a1l, p_wkh, p_wkl, nullptr, nullptr, p_kh,  p_kl,  DD, DD);
    mma_gemm<4><<<dim3(8, 32), 256>>>(p_a1h, p_a1l, p_wvh, p_wvl, nullptr, nullptr, p_vth, p_vtl, DD, DD);
    // 3. tensor-core causal flash attention -> split bf16 [B,S,D]
    attn_mma<<<dim3(SS/64, BB*HH), 128, ATT2_SMEM>>>(p_qh, p_ql, p_kh, p_kl, p_vth, p_vtl,
                                                     amask, p_ath, p_atl);
    // 4. Wo + residual -> x1
    mma_gemm<2><<<dim3(8, 32), 256>>>(p_ath, p_atl, p_woh, p_wol, p_x1, x, nullptr, nullptr, DD, DD);
    // 5. ln2 -> split bf16
    ln_bf16_kernel<<<ROWS, 256>>>(p_x1, gamma2, beta2, p_l2h, p_l2l);
    // 6. W1 (D -> 4D)
    mma_gemm<0><<<dim3(32, 32), 256>>>(p_l2h, p_l2l, p_w1h, p_w1l, p_h, nullptr, nullptr, nullptr, 4*DD, DD);
    // 7. GLU -> split bf16
    glu_kernel<<<(ROWS * 2 * DD / 4) / 256, 256>>>(p_h, p_gh, p_gl);
    // 8. W2 + residual -> out
    mma_gemm<2><<<dim3(8, 32), 256>>>(p_gh, p_gl, p_w2h, p_w2l, out, p_x1, nullptr, nullptr, DD, 2*DD);
}